// round 4
// baseline (speedup 1.0000x reference)
#include <cuda_runtime.h>

// TEPRNN2: fc1(1->4,tanh) -> LSTM(4->64) over S=256 -> fc2(64->1), B=4096.
// One hidden unit per thread, 8 batches per 2-warp group, f32x2 FMA mainloop.
// Round 4: forced group phase-skew so co-SMSP groups run FMA/ACT anti-phased,
//          hiding the activation (MUFU) tail under the other group's FMA window.

#define S_LEN   256
#define HID     64
#define BPB     32      // batches per block
#define RB      8       // batches per group
#define THREADS 256     // 4 groups x 64 threads
#define CHUNK   16      // fc1 precompute chunk (steps)
#define WSM_STRIDE 260  // 256 + 4 pad floats (bank-conflict-free LDS.128)
#define SKEW_ITERS 330  // ~1320 cyc per group of forced phase skew

typedef unsigned long long ull;

__device__ __forceinline__ void ffma2(ull &d, ull a, ull b) {
    asm volatile("fma.rn.f32x2 %0, %1, %2, %3;" : "=l"(d) : "l"(a), "l"(b), "l"(d));
}
__device__ __forceinline__ float2 unpk(ull v) {
    float2 r;
    asm("mov.b64 {%0, %1}, %2;" : "=f"(r.x), "=f"(r.y) : "l"(v));
    return r;
}
__device__ __forceinline__ float sigm_f(float x) {
    x = fminf(fmaxf(x, -30.f), 30.f);
    float e = __expf(-x);
    return __fdividef(1.f, 1.f + e);
}
__device__ __forceinline__ float tanh_f(float x) {
    x = fminf(fmaxf(x, -15.f), 15.f);
    float e = __expf(-2.f * x);
    return __fdividef(1.f - e, 1.f + e);
}
__device__ __forceinline__ void barg(int grp) {
    asm volatile("bar.sync %0, 64;" :: "r"(grp + 1) : "memory");
}

// Shared layout (floats):
//   Wsm   : [64][260]                               = 16640
//   group : 4 x { hsm[2][8][64]=1024, fc1c[8][16][4]=512 } = 6144
//   w2sm  : 64
#define GRP_FLOATS 1536
#define SMEM_FLOATS (16640 + 4 * GRP_FLOATS + 64)

extern __shared__ float smem[];

__global__ __launch_bounds__(THREADS, 1)
void teprnn2_kernel(const float* __restrict__ x,
                    const float* __restrict__ W1,
                    const float* __restrict__ b1,
                    const float* __restrict__ W_ih,
                    const float* __restrict__ W_hh,
                    const float* __restrict__ b_ih,
                    const float* __restrict__ b_hh,
                    const float* __restrict__ W2,
                    const float* __restrict__ b2,
                    float* __restrict__ out)
{
    float* Wsm   = smem;
    float* gbase = smem + 16640;
    float* w2sm  = smem + 16640 + 4 * GRP_FLOATS;

    const int tid  = threadIdx.x;
    const int grp  = tid >> 6;
    const int gtid = tid & 63;
    const int u    = gtid;

    float* hsm  = gbase + grp * GRP_FLOATS;   // [2][8][64]
    float* fc1c = hsm + 1024;                 // [8][16][4]

    // ---- Load W_hh reordered: Wsm[u][j*64 + k] = W_hh[(j*64+u)*64 + k] ----
    for (int i = tid; i < 16384; i += THREADS) {
        int row = i >> 6;
        int k   = i & 63;
        Wsm[(row & 63) * WSM_STRIDE + (row >> 6) * 64 + k] = W_hh[i];
    }
    if (tid < 64) w2sm[tid] = W2[tid];

    // zero h buffer 0 for this group
    #pragma unroll
    for (int b = 0; b < RB; ++b) hsm[b * 64 + u] = 0.f;

    // per-thread W_ih rows + combined bias for its unit
    float wih[4][4], bias[4];
    #pragma unroll
    for (int j = 0; j < 4; ++j) {
        int row = j * 64 + u;
        #pragma unroll
        for (int i = 0; i < 4; ++i) wih[j][i] = W_ih[row * 4 + i];
        bias[j] = b_ih[row] + b_hh[row];
    }

    // fc1 params (all 4 features in registers, every thread)
    float w1v[4], b1v[4];
    #pragma unroll
    for (int i = 0; i < 4; ++i) { w1v[i] = W1[i]; b1v[i] = b1[i]; }

    const int bbase = blockIdx.x * BPB + grp * RB;

    float c[RB];
    #pragma unroll
    for (int b = 0; b < RB; ++b) c[b] = 0.f;

    const float* Wu = Wsm + u * WSM_STRIDE;
    __syncthreads();   // Wsm + w2sm + h init visible to all groups (last block sync)

    // ---- forced phase skew: group g delayed by ~g*1320 cyc ----
    // Dependent FMA chain on a runtime value; bounded (|dummy| < ~1001), folded
    // into bias with *0.0f so it is neither dead code nor numerically active.
    {
        float dummy = fabsf(Wsm[gtid]);   // runtime, bounded ~[0, 4]
        const int iters = grp * SKEW_ITERS;
        #pragma unroll 1
        for (int i = 0; i < iters; ++i)
            dummy = fmaf(dummy, 0.999f, 1.0f);
        bias[0] += dummy * 0.0f;
    }

    for (int s0 = 0; s0 < S_LEN; s0 += CHUNK) {
        // ---- fc1 chunk: fc1c[b][si][0..3] = tanh(x[b][s0+si]*W1 + b1) ----
        #pragma unroll
        for (int q = 0; q < 2; ++q) {
            int p  = gtid * 2 + q;
            int b  = p >> 4;
            int si = p & 15;
            float xv = __ldg(x + (size_t)(bbase + b) * S_LEN + s0 + si);
            float4 t;
            t.x = tanh_f(fmaf(xv, w1v[0], b1v[0]));
            t.y = tanh_f(fmaf(xv, w1v[1], b1v[1]));
            t.z = tanh_f(fmaf(xv, w1v[2], b1v[2]));
            t.w = tanh_f(fmaf(xv, w1v[3], b1v[3]));
            *(float4*)(fc1c + p * 4) = t;
        }
        barg(grp);   // fc1 chunk visible to group

        #pragma unroll 2
        for (int si = 0; si < CHUNK; ++si) {
            const int    rbuf = si & 1;
            const float* hb   = hsm + rbuf * 512;

            ull acc[4][RB];
            #pragma unroll
            for (int j = 0; j < 4; ++j)
                #pragma unroll
                for (int b = 0; b < RB; ++b) acc[j][b] = 0ULL;

            // ---- recurrent matvec: gates += W_hh[:,k] * h[k] (f32x2) ----
            #pragma unroll
            for (int k4 = 0; k4 < 16; ++k4) {
                ulonglong2 w[4];
                #pragma unroll
                for (int j = 0; j < 4; ++j)
                    w[j] = *(const ulonglong2*)(Wu + j * 64 + k4 * 4);
                #pragma unroll
                for (int b = 0; b < RB; ++b) {
                    ulonglong2 hv = *(const ulonglong2*)(hb + b * 64 + k4 * 4);
                    #pragma unroll
                    for (int j = 0; j < 4; ++j) {
                        ffma2(acc[j][b], w[j].x, hv.x);
                        ffma2(acc[j][b], w[j].y, hv.y);
                    }
                }
            }

            // ---- gate activations + state update ----
            float* hw = hsm + (1 - rbuf) * 512;
            #pragma unroll
            for (int b = 0; b < RB; ++b) {
                float4 f4 = *(const float4*)(fc1c + (b * CHUNK + si) * 4);
                float pre[4];
                #pragma unroll
                for (int j = 0; j < 4; ++j) {
                    float2 p = unpk(acc[j][b]);
                    pre[j] = p.x + p.y + bias[j]
                           + wih[j][0] * f4.x + wih[j][1] * f4.y
                           + wih[j][2] * f4.z + wih[j][3] * f4.w;
                }
                float ig = sigm_f(pre[0]);
                float fg = sigm_f(pre[1]);
                float gg = tanh_f(pre[2]);
                float og = sigm_f(pre[3]);
                c[b] = fg * c[b] + ig * gg;
                hw[b * 64 + u] = og * tanh_f(c[b]);
            }
            barg(grp);   // h(next) visible to group
        }
    }

    // final h in buffer 0 (step 255 wrote 1-(255&1) = 0)
    if (gtid < RB) {
        const float* hf = hsm + gtid * 64;
        ull s2 = 0ULL;
        #pragma unroll
        for (int k = 0; k < 32; ++k)
            ffma2(s2, *(const ull*)(w2sm + k * 2), *(const ull*)(hf + k * 2));
        float2 sp = unpk(s2);
        out[bbase + gtid] = sp.x + sp.y + b2[0];
    }
}

extern "C" void kernel_launch(void* const* d_in, const int* in_sizes, int n_in,
                              void* d_out, int out_size)
{
    const float* x    = (const float*)d_in[0];
    const float* W1   = (const float*)d_in[1];
    const float* b1   = (const float*)d_in[2];
    const float* W_ih = (const float*)d_in[3];
    const float* W_hh = (const float*)d_in[4];
    const float* b_ih = (const float*)d_in[5];
    const float* b_hh = (const float*)d_in[6];
    const float* W2   = (const float*)d_in[7];
    const float* b2   = (const float*)d_in[8];
    float* out = (float*)d_out;

    const int smem_bytes = SMEM_FLOATS * (int)sizeof(float);
    cudaFuncSetAttribute(teprnn2_kernel,
                         cudaFuncAttributeMaxDynamicSharedMemorySize, smem_bytes);

    teprnn2_kernel<<<4096 / BPB, THREADS, smem_bytes>>>(
        x, W1, b1, W_ih, W_hh, b_ih, b_hh, W2, b2, out);
}

// round 5
// speedup vs baseline: 1.1556x; 1.1556x over previous
#include <cuda_runtime.h>

// TEPRNN2: fc1(1->4,tanh) -> LSTM(4->64) over S=256 -> fc2(64->1), B=4096.
// Round 5: 512 threads (8 groups x 64), RB=4 batches/group -> 4 warps/SMSP
// from 4 independent self-paced groups; acc shrinks to 32 regs so the whole
// block fits the RF at 16 warps/SM.

#define S_LEN   256
#define HID     64
#define BPB     32      // batches per block
#define RB      4       // batches per group
#define NGRP    8
#define THREADS 512     // 8 groups x 64 threads
#define CHUNK   16      // fc1 precompute chunk (steps)
#define WSM_STRIDE 260  // 256 + 4 pad floats (bank-conflict-free LDS.128)

typedef unsigned long long ull;

__device__ __forceinline__ void ffma2(ull &d, ull a, ull b) {
    asm volatile("fma.rn.f32x2 %0, %1, %2, %3;" : "=l"(d) : "l"(a), "l"(b), "l"(d));
}
__device__ __forceinline__ float2 unpk(ull v) {
    float2 r;
    asm("mov.b64 {%0, %1}, %2;" : "=f"(r.x), "=f"(r.y) : "l"(v));
    return r;
}
__device__ __forceinline__ float sigm_f(float x) {
    x = fminf(fmaxf(x, -30.f), 30.f);
    float e = __expf(-x);
    return __fdividef(1.f, 1.f + e);
}
__device__ __forceinline__ float tanh_f(float x) {
    x = fminf(fmaxf(x, -15.f), 15.f);
    float e = __expf(-2.f * x);
    return __fdividef(1.f - e, 1.f + e);
}
__device__ __forceinline__ void barg(int grp) {
    asm volatile("bar.sync %0, 64;" :: "r"(grp + 1) : "memory");
}

// Shared layout (floats):
//   Wsm   : [64][260]                                  = 16640
//   group : 8 x { hsm[2][4][64]=512, fc1c[4][16][4]=256 } = 6144
//   w2sm  : 64
#define GRP_FLOATS 768
#define SMEM_FLOATS (16640 + NGRP * GRP_FLOATS + 64)

extern __shared__ float smem[];

__global__ __launch_bounds__(THREADS, 1)
void teprnn2_kernel(const float* __restrict__ x,
                    const float* __restrict__ W1,
                    const float* __restrict__ b1,
                    const float* __restrict__ W_ih,
                    const float* __restrict__ W_hh,
                    const float* __restrict__ b_ih,
                    const float* __restrict__ b_hh,
                    const float* __restrict__ W2,
                    const float* __restrict__ b2,
                    float* __restrict__ out)
{
    float* Wsm   = smem;
    float* gbase = smem + 16640;
    float* w2sm  = smem + 16640 + NGRP * GRP_FLOATS;

    const int tid  = threadIdx.x;
    const int grp  = tid >> 6;
    const int gtid = tid & 63;
    const int u    = gtid;

    float* hsm  = gbase + grp * GRP_FLOATS;   // [2][4][64]
    float* fc1c = hsm + 512;                  // [4][16][4]

    // ---- Load W_hh reordered: Wsm[u][j*64 + k] = W_hh[(j*64+u)*64 + k] ----
    for (int i = tid; i < 16384; i += THREADS) {
        int row = i >> 6;
        int k   = i & 63;
        Wsm[(row & 63) * WSM_STRIDE + (row >> 6) * 64 + k] = W_hh[i];
    }
    if (tid < 64) w2sm[tid] = W2[tid];

    // zero h buffer 0 for this group
    #pragma unroll
    for (int b = 0; b < RB; ++b) hsm[b * 64 + u] = 0.f;

    // per-thread W_ih rows + combined bias for its unit
    float wih[4][4], bias[4];
    #pragma unroll
    for (int j = 0; j < 4; ++j) {
        int row = j * 64 + u;
        #pragma unroll
        for (int i = 0; i < 4; ++i) wih[j][i] = W_ih[row * 4 + i];
        bias[j] = b_ih[row] + b_hh[row];
    }

    // fc1 params (all 4 features in registers, every thread)
    float w1v[4], b1v[4];
    #pragma unroll
    for (int i = 0; i < 4; ++i) { w1v[i] = W1[i]; b1v[i] = b1[i]; }

    const int bbase = blockIdx.x * BPB + grp * RB;

    float c[RB];
    #pragma unroll
    for (int b = 0; b < RB; ++b) c[b] = 0.f;

    const float* Wu = Wsm + u * WSM_STRIDE;
    __syncthreads();   // Wsm + w2sm + h init visible

    for (int s0 = 0; s0 < S_LEN; s0 += CHUNK) {
        // ---- fc1 chunk: fc1c[b][si][0..3] = tanh(x[b][s0+si]*W1 + b1) ----
        // 4b x 16si = 64 float4 slots; one per thread.
        {
            int b  = gtid >> 4;
            int si = gtid & 15;
            float xv = __ldg(x + (size_t)(bbase + b) * S_LEN + s0 + si);
            float4 t;
            t.x = tanh_f(fmaf(xv, w1v[0], b1v[0]));
            t.y = tanh_f(fmaf(xv, w1v[1], b1v[1]));
            t.z = tanh_f(fmaf(xv, w1v[2], b1v[2]));
            t.w = tanh_f(fmaf(xv, w1v[3], b1v[3]));
            *(float4*)(fc1c + gtid * 4) = t;
        }
        barg(grp);   // fc1 chunk visible to group

        #pragma unroll 2
        for (int si = 0; si < CHUNK; ++si) {
            const int    rbuf = si & 1;       // s0 is even multiple of CHUNK
            const float* hb   = hsm + rbuf * (RB * 64);

            ull acc[4][RB];
            #pragma unroll
            for (int j = 0; j < 4; ++j)
                #pragma unroll
                for (int b = 0; b < RB; ++b) acc[j][b] = 0ULL;

            // ---- recurrent matvec: gates += W_hh[:,k] * h[k] (f32x2) ----
            #pragma unroll
            for (int k4 = 0; k4 < 16; ++k4) {
                ulonglong2 w[4];
                #pragma unroll
                for (int j = 0; j < 4; ++j)
                    w[j] = *(const ulonglong2*)(Wu + j * 64 + k4 * 4);
                #pragma unroll
                for (int b = 0; b < RB; ++b) {
                    ulonglong2 hv = *(const ulonglong2*)(hb + b * 64 + k4 * 4);
                    #pragma unroll
                    for (int j = 0; j < 4; ++j) {
                        ffma2(acc[j][b], w[j].x, hv.x);
                        ffma2(acc[j][b], w[j].y, hv.y);
                    }
                }
            }

            // ---- gate activations + state update ----
            float* hw = hsm + (1 - rbuf) * (RB * 64);
            #pragma unroll
            for (int b = 0; b < RB; ++b) {
                float4 f4 = *(const float4*)(fc1c + (b * CHUNK + si) * 4);
                float pre[4];
                #pragma unroll
                for (int j = 0; j < 4; ++j) {
                    float2 p = unpk(acc[j][b]);
                    pre[j] = p.x + p.y + bias[j]
                           + wih[j][0] * f4.x + wih[j][1] * f4.y
                           + wih[j][2] * f4.z + wih[j][3] * f4.w;
                }
                float ig = sigm_f(pre[0]);
                float fg = sigm_f(pre[1]);
                float gg = tanh_f(pre[2]);
                float og = sigm_f(pre[3]);
                c[b] = fg * c[b] + ig * gg;
                hw[b * 64 + u] = og * tanh_f(c[b]);
            }
            barg(grp);   // h(next) visible to group
        }
    }

    // final h in buffer 0 (step 255: si=15 -> wrote 1-(15&1) = 0)
    if (gtid < RB) {
        const float* hf = hsm + gtid * 64;
        ull s2 = 0ULL;
        #pragma unroll
        for (int k = 0; k < 32; ++k)
            ffma2(s2, *(const ull*)(w2sm + k * 2), *(const ull*)(hf + k * 2));
        float2 sp = unpk(s2);
        out[bbase + gtid] = sp.x + sp.y + b2[0];
    }
}

extern "C" void kernel_launch(void* const* d_in, const int* in_sizes, int n_in,
                              void* d_out, int out_size)
{
    const float* x    = (const float*)d_in[0];
    const float* W1   = (const float*)d_in[1];
    const float* b1   = (const float*)d_in[2];
    const float* W_ih = (const float*)d_in[3];
    const float* W_hh = (const float*)d_in[4];
    const float* b_ih = (const float*)d_in[5];
    const float* b_hh = (const float*)d_in[6];
    const float* W2   = (const float*)d_in[7];
    const float* b2   = (const float*)d_in[8];
    float* out = (float*)d_out;

    const int smem_bytes = SMEM_FLOATS * (int)sizeof(float);
    cudaFuncSetAttribute(teprnn2_kernel,
                         cudaFuncAttributeMaxDynamicSharedMemorySize, smem_bytes);

    teprnn2_kernel<<<4096 / BPB, THREADS, smem_bytes>>>(
        x, W1, b1, W_ih, W_hh, b_ih, b_hh, W2, b2, out);
}

// round 7
// speedup vs baseline: 2.2781x; 1.9714x over previous
#include <cuda_runtime.h>
#include <cuda_fp16.h>
#include <cstdint>

// TEPRNN2 via legacy warp MMA (HMMA): gates[256,32] = [W_hh|W_ih|bias] x [h|fc1|1]
// fp16 hi/lo 2-term split (3 MMAs) for fp32-grade precision; W stationary in
// registers as A-fragments; fully register-local LSTM epilogue.

#define S_LEN   256
#define THREADS 256
#define BPB     32
#define HST     88          // halfs per batch column (80 + 8 pad; conflict-free)

__device__ __forceinline__ float sigm_f(float x){
    x = fminf(fmaxf(x, -30.f), 30.f);
    float e = __expf(-x);
    return __fdividef(1.f, 1.f + e);
}
__device__ __forceinline__ float tanh_f(float x){
    x = fminf(fmaxf(x, -15.f), 15.f);
    float e = __expf(-2.f * x);
    return __fdividef(1.f - e, 1.f + e);
}
__device__ __forceinline__ uint32_t pk(float a, float b){
    __half2 t = __halves2half2(__float2half_rn(a), __float2half_rn(b));
    return *reinterpret_cast<uint32_t*>(&t);
}
__device__ __forceinline__ void mma16816(float* d, const uint32_t* a,
                                         uint32_t b0, uint32_t b1){
    asm volatile(
        "mma.sync.aligned.m16n8k16.row.col.f32.f16.f16.f32 "
        "{%0,%1,%2,%3}, {%4,%5,%6,%7}, {%8,%9}, {%0,%1,%2,%3};"
        : "+f"(d[0]), "+f"(d[1]), "+f"(d[2]), "+f"(d[3])
        : "r"(a[0]), "r"(a[1]), "r"(a[2]), "r"(a[3]), "r"(b0), "r"(b1));
}

__global__ __launch_bounds__(THREADS, 1)
void teprnn2_mma(const float* __restrict__ x,
                 const float* __restrict__ W1,
                 const float* __restrict__ b1,
                 const float* __restrict__ W_ih,
                 const float* __restrict__ W_hh,
                 const float* __restrict__ b_ih,
                 const float* __restrict__ b_hh,
                 const float* __restrict__ W2,
                 const float* __restrict__ b2,
                 float* __restrict__ out)
{
    __shared__ __half hHI[2][2][16][HST];   // [npair][buf][batch-col][k]
    __shared__ __half hLO[2][2][16][HST];
    __shared__ float  hfin[32][65];

    const int tid  = threadIdx.x;
    const int w    = tid >> 5;
    const int lane = tid & 31;
    const int ub   = w & 3;        // unit block (16 units)
    const int np   = w >> 2;       // batch half (0: cols 0-15, 1: 16-31)
    const int r0   = lane >> 2;    // row within tile
    const int k0   = (lane & 3) * 2;
    const int bbase = blockIdx.x * BPB;

    // ---- A fragments: Ah/Al[gate][ktile][4], kt=4 uses slots 0,1 only ----
    uint32_t Ah[4][5][4], Al[4][5][4];
    {
        #pragma unroll
        for (int g = 0; g < 4; ++g) {
            const int gr0 = g * 64 + ub * 16 + r0;
            #pragma unroll
            for (int kt = 0; kt < 5; ++kt) {
                const int kb = kt * 16 + k0;
                float v[8];
                if (kt < 4) {
                    v[0] = W_hh[gr0 * 64 + kb];       v[1] = W_hh[gr0 * 64 + kb + 1];
                    v[2] = W_hh[(gr0+8) * 64 + kb];   v[3] = W_hh[(gr0+8) * 64 + kb + 1];
                    v[4] = W_hh[gr0 * 64 + kb + 8];   v[5] = W_hh[gr0 * 64 + kb + 9];
                    v[6] = W_hh[(gr0+8) * 64 + kb+8]; v[7] = W_hh[(gr0+8) * 64 + kb + 9];
                } else {
                    #pragma unroll
                    for (int e = 0; e < 8; ++e) v[e] = 0.f;
                    const int ka = 64 + k0, kb2 = ka + 1;
                    // rows gr0 and gr0+8, k = ka, ka+1 (64..71); 68 = bias, >68 = 0
                    float va = (ka  < 68) ? W_ih[gr0*4 + (ka-64)]     : (ka  == 68 ? b_ih[gr0]   + b_hh[gr0]   : 0.f);
                    float vb = (kb2 < 68) ? W_ih[gr0*4 + (kb2-64)]    : (kb2 == 68 ? b_ih[gr0]   + b_hh[gr0]   : 0.f);
                    float vc = (ka  < 68) ? W_ih[(gr0+8)*4 + (ka-64)] : (ka  == 68 ? b_ih[gr0+8] + b_hh[gr0+8] : 0.f);
                    float vd = (kb2 < 68) ? W_ih[(gr0+8)*4 + (kb2-64)]: (kb2 == 68 ? b_ih[gr0+8] + b_hh[gr0+8] : 0.f);
                    v[0] = va; v[1] = vb; v[2] = vc; v[3] = vd;
                }
                float hi[8], lo[8];
                #pragma unroll
                for (int e = 0; e < 8; ++e) {
                    hi[e] = __half2float(__float2half_rn(v[e]));
                    lo[e] = v[e] - hi[e];
                }
                Ah[g][kt][0] = pk(hi[0], hi[1]);  Al[g][kt][0] = pk(lo[0], lo[1]);
                Ah[g][kt][1] = pk(hi[2], hi[3]);  Al[g][kt][1] = pk(lo[2], lo[3]);
                Ah[g][kt][2] = pk(hi[4], hi[5]);  Al[g][kt][2] = pk(lo[4], lo[5]);
                Ah[g][kt][3] = pk(hi[6], hi[7]);  Al[g][kt][3] = pk(lo[6], lo[7]);
            }
        }
    }

    // ---- fc1 duty + SMEM init ----
    const int lt = tid & 127;
    const int lb = lt >> 3;            // local batch 0..15
    const int fi = (lt >> 1) & 3;      // feature
    const int pr = lt & 1;             // 0 = hi, 1 = lo
    const float w1r = __ldg(W1 + fi);
    const float b1r = __ldg(b1 + fi);
    const float* xrow = x + (size_t)(bbase + np * 16 + lb) * S_LEN;

    {   // zero both B arrays
        __half* p0 = &hHI[0][0][0][0];
        __half* p1 = &hLO[0][0][0][0];
        for (int i = tid; i < 2 * 2 * 16 * HST; i += THREADS) { p0[i] = __ushort_as_half(0); p1[i] = __ushort_as_half(0); }
    }
    __syncthreads();
    if (tid < 64) {  // const-1 row (k=68) in both bufs, both halves
        int idx = tid >> 4;
        hHI[idx >> 1][idx & 1][tid & 15][68] = __float2half_rn(1.f);
    }
    {   // fc1 for step 0 -> buf 0
        float v  = tanh_f(fmaf(__ldg(xrow + 0), w1r, b1r));
        float vh = __half2float(__float2half_rn(v));
        if (pr == 0) hHI[np][0][lb][64 + fi] = __float2half_rn(v);
        else         hLO[np][0][lb][64 + fi] = __float2half_rn(v - vh);
    }
    __syncthreads();

    float cst[2][4];
    #pragma unroll
    for (int nt = 0; nt < 2; ++nt)
        #pragma unroll
        for (int e = 0; e < 4; ++e) cst[nt][e] = 0.f;

    int buf = 0;
    for (int s = 0; s < S_LEN; ++s) {
        float xv = (s + 1 < S_LEN) ? __ldg(xrow + s + 1) : 0.f;

        float d[4][2][4];
        #pragma unroll
        for (int g = 0; g < 4; ++g)
            #pragma unroll
            for (int nt = 0; nt < 2; ++nt)
                #pragma unroll
                for (int e = 0; e < 4; ++e) d[g][nt][e] = 0.f;

        const __half* bhp = &hHI[np][buf][0][0];
        const __half* blp = &hLO[np][buf][0][0];

        #pragma unroll
        for (int kt = 0; kt < 4; ++kt) {
            #pragma unroll
            for (int nt = 0; nt < 2; ++nt) {
                const int idx = (nt * 8 + r0) * HST + kt * 16 + k0;
                uint32_t bh0 = *(const uint32_t*)(bhp + idx);
                uint32_t bh1 = *(const uint32_t*)(bhp + idx + 8);
                uint32_t bl0 = *(const uint32_t*)(blp + idx);
                uint32_t bl1 = *(const uint32_t*)(blp + idx + 8);
                #pragma unroll
                for (int g = 0; g < 4; ++g) {
                    mma16816(d[g][nt], Ah[g][kt], bh0, bh1);
                    mma16816(d[g][nt], Al[g][kt], bh0, bh1);
                    mma16816(d[g][nt], Ah[g][kt], bl0, bl1);
                }
            }
        }
        {   // kt = 4 (fc1 + bias rows 64..79; rows 72+ are zero)
            #pragma unroll
            for (int nt = 0; nt < 2; ++nt) {
                const int idx = (nt * 8 + r0) * HST + 64 + k0;
                uint32_t bh0 = *(const uint32_t*)(bhp + idx);
                uint32_t bl0 = *(const uint32_t*)(blp + idx);
                #pragma unroll
                for (int g = 0; g < 4; ++g) {
                    mma16816(d[g][nt], Ah[g][4], bh0, 0u);
                    mma16816(d[g][nt], Al[g][4], bh0, 0u);
                    mma16816(d[g][nt], Ah[g][4], bl0, 0u);
                }
            }
        }

        // ---- LSTM epilogue (register-local gates) ----
        const int nbuf = buf ^ 1;
        #pragma unroll
        for (int nt = 0; nt < 2; ++nt) {
            #pragma unroll
            for (int e = 0; e < 4; ++e) {
                float gi = d[0][nt][e], gf = d[1][nt][e];
                float gg = d[2][nt][e], go = d[3][nt][e];
                float cc = sigm_f(gf) * cst[nt][e] + sigm_f(gi) * tanh_f(gg);
                cst[nt][e] = cc;
                float hh = sigm_f(go) * tanh_f(cc);
                const int u  = ub * 16 + r0 + ((e >= 2) ? 8 : 0);
                const int cl = nt * 8 + k0 + (e & 1);
                float hhi = __half2float(__float2half_rn(hh));
                hHI[np][nbuf][cl][u] = __float2half_rn(hh);
                hLO[np][nbuf][cl][u] = __float2half_rn(hh - hhi);
                if (s == S_LEN - 1) hfin[np * 16 + cl][u] = hh;
            }
        }

        // fc1 for step s+1 -> nbuf
        if (s + 1 < S_LEN) {
            float v  = tanh_f(fmaf(xv, w1r, b1r));
            float vh = __half2float(__float2half_rn(v));
            if (pr == 0) hHI[np][nbuf][lb][64 + fi] = __float2half_rn(v);
            else         hLO[np][nbuf][lb][64 + fi] = __float2half_rn(v - vh);
        }

        asm volatile("bar.sync %0, 128;" :: "r"(np + 1) : "memory");
        buf ^= 1;
    }

    __syncthreads();

    // ---- fc2 ----
    if (tid < 32) {
        float acc = __ldg(b2);
        #pragma unroll
        for (int u = 0; u < 64; ++u)
            acc = fmaf(__ldg(W2 + u), hfin[tid][u], acc);
        out[bbase + tid] = acc;
    }
}

extern "C" void kernel_launch(void* const* d_in, const int* in_sizes, int n_in,
                              void* d_out, int out_size)
{
    const float* x    = (const float*)d_in[0];
    const float* W1   = (const float*)d_in[1];
    const float* b1   = (const float*)d_in[2];
    const float* W_ih = (const float*)d_in[3];
    const float* W_hh = (const float*)d_in[4];
    const float* b_ih = (const float*)d_in[5];
    const float* b_hh = (const float*)d_in[6];
    const float* W2   = (const float*)d_in[7];
    const float* b2   = (const float*)d_in[8];
    float* out = (float*)d_out;

    teprnn2_mma<<<4096 / BPB, THREADS>>>(
        x, W1, b1, W_ih, W_hh, b_ih, b_hh, W2, b2, out);
}